// round 10
// baseline (speedup 1.0000x reference)
#include <cuda_runtime.h>
#include <cuda_bf16.h>
#include <cstdint>

#define NUM_HEAD 12
#define BATCH    16
#define SEQ      1024
#define DHEAD    64
#define EMB      768
#define QKVN     2304   // 3 * 12 * 64
#define NTOK     (BATCH * SEQ)

// ======================= scratch (device globals) ==========================
__device__ __nv_bfloat16 g_z_hi[NTOK * EMB];                      // z split [tok][e]
__device__ __nv_bfloat16 g_z_lo[NTOK * EMB];
__device__ __nv_bfloat16 g_q_hi[NUM_HEAD * BATCH * SEQ * DHEAD];  // [h][b][n][d]
__device__ __nv_bfloat16 g_q_lo[NUM_HEAD * BATCH * SEQ * DHEAD];
__device__ __nv_bfloat16 g_k_hi[NUM_HEAD * BATCH * SEQ * DHEAD];
__device__ __nv_bfloat16 g_k_lo[NUM_HEAD * BATCH * SEQ * DHEAD];
__device__ __nv_bfloat16 g_v_hi[NUM_HEAD * BATCH * SEQ * DHEAD];
__device__ __nv_bfloat16 g_v_lo[NUM_HEAD * BATCH * SEQ * DHEAD];
__device__ __nv_bfloat16 g_o_hi[NTOK * EMB];                      // attn out split [tok][h*d]
__device__ __nv_bfloat16 g_o_lo[NTOK * EMB];
__device__ __nv_bfloat16 g_Wq_hi[QKVN * EMB];                     // QKV weights T [c][e]
__device__ __nv_bfloat16 g_Wq_lo[QKVN * EMB];
__device__ __nv_bfloat16 g_Wm_hi[EMB * EMB];                      // Umsa T [n][e]
__device__ __nv_bfloat16 g_Wm_lo[EMB * EMB];

// ======================= split helpers =====================================
__device__ __forceinline__ __nv_bfloat162 split_hi(float a, float b, __nv_bfloat162& lo) {
    __nv_bfloat162 hi;
    hi.x = __float2bfloat16(a);
    hi.y = __float2bfloat16(b);
    lo.x = __float2bfloat16(a - __bfloat162float(hi.x));
    lo.y = __float2bfloat16(b - __bfloat162float(hi.y));
    return hi;
}
__device__ __forceinline__ uint32_t pack_split(float a, float b, uint32_t& lo_u) {
    __nv_bfloat162 lo;
    __nv_bfloat162 hi = split_hi(a, b, lo);
    lo_u = *(uint32_t*)&lo;
    return *(uint32_t*)&hi;
}

// ---------------- packing kernels ------------------------------------------
__global__ void pack_z_kernel(const float* __restrict__ z) {
    int idx = blockIdx.x * blockDim.x + threadIdx.x;   // over NTOK*EMB/2
    if (idx >= NTOK * EMB / 2) return;
    float2 v = *(const float2*)(z + idx * 2);
    __nv_bfloat162 lo;
    __nv_bfloat162 hi = split_hi(v.x, v.y, lo);
    *(__nv_bfloat162*)(g_z_hi + idx * 2) = hi;
    *(__nv_bfloat162*)(g_z_lo + idx * 2) = lo;
}
__global__ void pack_qkv_kernel(const float* __restrict__ U) {
    int idx = blockIdx.x * blockDim.x + threadIdx.x;
    if (idx >= QKVN * EMB) return;
    int c = idx / EMB, e = idx - c * EMB;
    int h = c / 192, rem = c - h * 192;
    int r = rem >> 6, d = rem & 63;
    float v = U[((h * 3 + r) * EMB + e) * DHEAD + d];
    __nv_bfloat16 hi = __float2bfloat16(v);
    g_Wq_hi[idx] = hi;
    g_Wq_lo[idx] = __float2bfloat16(v - __bfloat162float(hi));
}
__global__ void pack_msa_kernel(const float* __restrict__ U) {
    int idx = blockIdx.x * blockDim.x + threadIdx.x;
    if (idx >= EMB * EMB) return;
    int n = idx / EMB, e = idx - n * EMB;
    float v = U[e * EMB + n];
    __nv_bfloat16 hi = __float2bfloat16(v);
    g_Wm_hi[idx] = hi;
    g_Wm_lo[idx] = __float2bfloat16(v - __bfloat162float(hi));
}

// ======================= warp-MMA / async helpers ==========================
__device__ __forceinline__ void ldsm_x4(uint32_t& r0, uint32_t& r1, uint32_t& r2, uint32_t& r3,
                                        uint32_t addr) {
    asm volatile("ldmatrix.sync.aligned.m8n8.x4.shared.b16 {%0,%1,%2,%3}, [%4];"
                 : "=r"(r0), "=r"(r1), "=r"(r2), "=r"(r3)
                 : "r"(addr));
}
__device__ __forceinline__ void ldsm_x4_t(uint32_t& r0, uint32_t& r1, uint32_t& r2, uint32_t& r3,
                                          uint32_t addr) {
    asm volatile("ldmatrix.sync.aligned.m8n8.x4.trans.shared.b16 {%0,%1,%2,%3}, [%4];"
                 : "=r"(r0), "=r"(r1), "=r"(r2), "=r"(r3)
                 : "r"(addr));
}
__device__ __forceinline__ void mma_bf16(float* c, const uint32_t* a, uint32_t b0, uint32_t b1) {
    asm volatile(
        "mma.sync.aligned.m16n8k16.row.col.f32.bf16.bf16.f32 "
        "{%0,%1,%2,%3}, {%4,%5,%6,%7}, {%8,%9}, {%0,%1,%2,%3};"
        : "+f"(c[0]), "+f"(c[1]), "+f"(c[2]), "+f"(c[3])
        : "r"(a[0]), "r"(a[1]), "r"(a[2]), "r"(a[3]), "r"(b0), "r"(b1));
}
__device__ __forceinline__ void cp_async16(uint32_t smem_addr, const void* gptr) {
    asm volatile("cp.async.cg.shared.global [%0], [%1], 16;" :: "r"(smem_addr), "l"(gptr));
}
#define CP_COMMIT() asm volatile("cp.async.commit_group;" ::: "memory")
#define CP_WAIT0()  asm volatile("cp.async.wait_group 0;" ::: "memory")

// ===== split-bf16 HMMA GEMM: C = A * B^T, 128x128 tile, all-async loads ====
// A,B both pre-split bf16 hi/lo [rows][768]. 256 thr, 8 warps (4m x 2n).
#define AST   40
#define G_AH  0
#define G_AL  (128 * AST)
#define G_BH  (2 * 128 * AST)
#define G_BL  (3 * 128 * AST)
#define G_BUF (4 * 128 * AST)          // 20480 elems per buffer
#define GEMM_SMEM (2 * G_BUF * 2)      // 81920 bytes

template <int NC, int MODE>
__global__ void __launch_bounds__(256, 2) hmma_gemm_kernel(float* __restrict__ Cp) {
    extern __shared__ __nv_bfloat16 gsm[];
    const int t = threadIdx.x, w = t >> 5, l = t & 31;
    const int n0 = blockIdx.x * 128, m0 = blockIdx.y * 128;
    const int wm = w >> 1, wn = w & 1;

    const __nv_bfloat16* Ahg = (MODE == 1) ? g_z_hi : g_o_hi;
    const __nv_bfloat16* Alg = (MODE == 1) ? g_z_lo : g_o_lo;
    const __nv_bfloat16* Bhg = (MODE == 1) ? g_Wq_hi : g_Wm_hi;
    const __nv_bfloat16* Blg = (MODE == 1) ? g_Wq_lo : g_Wm_lo;

    float acc[2][8][4];
#pragma unroll
    for (int mt = 0; mt < 2; mt++)
#pragma unroll
        for (int nt = 0; nt < 8; nt++)
#pragma unroll
            for (int r = 0; r < 4; r++) acc[mt][nt][r] = 0.0f;

    const uint32_t smB = (uint32_t)__cvta_generic_to_shared(gsm);

    const int aRow = wm * 32 + (l & 15);            // + mt*16
    const int aCol = (l >> 4) << 3;
    const int bRowOff = (l & 7) + ((l >> 4) << 3);  // + wn*64 + g2*16
    const int bCol = ((l >> 3) & 1) << 3;

    const int prow = t >> 2, pc8 = (t & 3) << 3;    // tile loader: 64 rows/pass

    auto cpTiles = [&](int kc, uint32_t bufEl) {
#pragma unroll
        for (int i = 0; i < 2; i++) {
            int row = prow + i * 64;
            uint32_t off = 2u * (uint32_t)(row * AST + pc8);
            cp_async16(smB + 2u * (bufEl + G_AH) + off, Ahg + (long)(m0 + row) * 768 + kc + pc8);
            cp_async16(smB + 2u * (bufEl + G_AL) + off, Alg + (long)(m0 + row) * 768 + kc + pc8);
            cp_async16(smB + 2u * (bufEl + G_BH) + off, Bhg + (long)(n0 + row) * 768 + kc + pc8);
            cp_async16(smB + 2u * (bufEl + G_BL) + off, Blg + (long)(n0 + row) * 768 + kc + pc8);
        }
    };

    cpTiles(0, 0);
    CP_COMMIT();
    CP_WAIT0();
    __syncthreads();

    for (int c = 0; c < 24; c++) {
        const uint32_t cur = (uint32_t)(c & 1) * G_BUF;
        const uint32_t nxt = (uint32_t)((c + 1) & 1) * G_BUF;
        if (c < 23) {
            cpTiles((c + 1) * 32, nxt);
            CP_COMMIT();
        }

        const uint32_t aHB = smB + 2u * (cur + G_AH), aLB = smB + 2u * (cur + G_AL);
        const uint32_t bHB = smB + 2u * (cur + G_BH), bLB = smB + 2u * (cur + G_BL);
#pragma unroll
        for (int ks = 0; ks < 2; ks++) {
            const int k0 = ks * 16;
            uint32_t ah[2][4], al[2][4], bh[4][4], bl[4][4];
#pragma unroll
            for (int mt = 0; mt < 2; mt++) {
                uint32_t off = 2u * (uint32_t)((aRow + mt * 16) * AST + k0 + aCol);
                ldsm_x4(ah[mt][0], ah[mt][1], ah[mt][2], ah[mt][3], aHB + off);
                ldsm_x4(al[mt][0], al[mt][1], al[mt][2], al[mt][3], aLB + off);
            }
#pragma unroll
            for (int g2 = 0; g2 < 4; g2++) {
                uint32_t off =
                    2u * (uint32_t)((wn * 64 + g2 * 16 + bRowOff) * AST + k0 + bCol);
                ldsm_x4(bh[g2][0], bh[g2][1], bh[g2][2], bh[g2][3], bHB + off);
                ldsm_x4(bl[g2][0], bl[g2][1], bl[g2][2], bl[g2][3], bLB + off);
            }
#pragma unroll
            for (int mt = 0; mt < 2; mt++)
#pragma unroll
                for (int nt = 0; nt < 8; nt++) {
                    const int g2 = nt >> 1, p = (nt & 1) * 2;
                    mma_bf16(acc[mt][nt], ah[mt], bh[g2][p], bh[g2][p + 1]);
                    mma_bf16(acc[mt][nt], ah[mt], bl[g2][p], bl[g2][p + 1]);
                    mma_bf16(acc[mt][nt], al[mt], bh[g2][p], bh[g2][p + 1]);
                }
        }

        if (c < 23) CP_WAIT0();
        __syncthreads();
    }

    // ---- epilogue
    const int rBase = m0 + wm * 32 + (l >> 2);
    const int cBase = wn * 64 + 2 * (l & 3);
    if (MODE == 2) {
#pragma unroll
        for (int mt = 0; mt < 2; mt++)
#pragma unroll
            for (int nt = 0; nt < 8; nt++) {
                int rA = rBase + mt * 16;
                int c = n0 + cBase + nt * 8;
                *(float2*)(Cp + (long)rA * NC + c) = make_float2(acc[mt][nt][0], acc[mt][nt][1]);
                *(float2*)(Cp + (long)(rA + 8) * NC + c) =
                    make_float2(acc[mt][nt][2], acc[mt][nt][3]);
            }
    } else {
        // QKV epilogue: q/k/v in natural [h][b][n][d] bf16 hi/lo
        const int g = (n0 + wn * 64) >> 6;  // h*3 + r
        const int h = g / 3, r = g - h * 3;
        __nv_bfloat16* dh = (r == 0 ? g_q_hi : (r == 1 ? g_k_hi : g_v_hi));
        __nv_bfloat16* dl = (r == 0 ? g_q_lo : (r == 1 ? g_k_lo : g_v_lo));
#pragma unroll
        for (int mt = 0; mt < 2; mt++) {
            int m = rBase + mt * 16;
            int b = m >> 10, tok = m & 1023;
            int hb = h * BATCH + b;
#pragma unroll
            for (int nt = 0; nt < 8; nt++) {
                int d = 2 * (l & 3) + nt * 8;
                long i0 = ((long)hb * SEQ + tok) * DHEAD + d;
                __nv_bfloat162 lo01, lo23;
                __nv_bfloat162 hi01 = split_hi(acc[mt][nt][0], acc[mt][nt][1], lo01);
                __nv_bfloat162 hi23 = split_hi(acc[mt][nt][2], acc[mt][nt][3], lo23);
                *(__nv_bfloat162*)(dh + i0) = hi01;
                *(__nv_bfloat162*)(dl + i0) = lo01;
                *(__nv_bfloat162*)(dh + i0 + 8 * DHEAD) = hi23;
                *(__nv_bfloat162*)(dl + i0 + 8 * DHEAD) = lo23;
            }
        }
    }
}

// ========= flash attention: FA2 + cp.async; V natural via ldsm.trans =======
#define FST 72
#define FQ_H 0
#define FQ_L (128 * FST)
#define FKV0 (2 * 128 * FST)
#define KV_KL (64 * FST)
#define KV_VH (2 * 64 * FST)
#define KV_VL (3 * 64 * FST)
#define KV_BUF (4 * 64 * FST)
#define FLASH_SMEM ((2 * 128 * FST + 2 * KV_BUF) * 2)   // 110592 bytes

__global__ void __launch_bounds__(256, 2) flash_kernel() {
    extern __shared__ __nv_bfloat16 sm[];
    const int t = threadIdx.x, w = t >> 5, l = t & 31;
    const int h = blockIdx.z, b = blockIdx.y, q0 = blockIdx.x * 128;
    const int hb = h * BATCH + b;
    const float SC = 0.125f * 1.4426950408889634f;

    const __nv_bfloat16* Qh = g_q_hi + ((long)hb * SEQ + q0) * DHEAD;
    const __nv_bfloat16* Ql = g_q_lo + ((long)hb * SEQ + q0) * DHEAD;
    const __nv_bfloat16* Kh = g_k_hi + (long)hb * SEQ * DHEAD;
    const __nv_bfloat16* Kl = g_k_lo + (long)hb * SEQ * DHEAD;
    const __nv_bfloat16* Vh = g_v_hi + (long)hb * SEQ * DHEAD;
    const __nv_bfloat16* Vl = g_v_lo + (long)hb * SEQ * DHEAD;

    const uint32_t smB = (uint32_t)__cvta_generic_to_shared(sm);
    const int lrow = t >> 3, lc8 = (t & 7) << 3;

    auto cpKV = [&](int kb, uint32_t bufEl) {
#pragma unroll
        for (int i = 0; i < 2; i++) {
            int row = lrow + i * 32;
            uint32_t off = 2u * (uint32_t)(row * FST + lc8);
            cp_async16(smB + 2u * bufEl + off, Kh + (long)(kb + row) * DHEAD + lc8);
            cp_async16(smB + 2u * (bufEl + KV_KL) + off, Kl + (long)(kb + row) * DHEAD + lc8);
            cp_async16(smB + 2u * (bufEl + KV_VH) + off, Vh + (long)(kb + row) * DHEAD + lc8);
            cp_async16(smB + 2u * (bufEl + KV_VL) + off, Vl + (long)(kb + row) * DHEAD + lc8);
        }
    };

    cpKV(0, FKV0);
    CP_COMMIT();
#pragma unroll
    for (int i = 0; i < 4; i++) {
        int idx = t + i * 256;
        int row = idx >> 3, c8 = (idx & 7) << 3;
        *(uint4*)&sm[FQ_H + row * FST + c8] = *(const uint4*)(Qh + row * DHEAD + c8);
        *(uint4*)&sm[FQ_L + row * FST + c8] = *(const uint4*)(Ql + row * DHEAD + c8);
    }
    CP_WAIT0();
    __syncthreads();

    float m_[2], l_[2], o_[8][4];
    m_[0] = m_[1] = -1e30f;
    l_[0] = l_[1] = 0.0f;
#pragma unroll
    for (int nt = 0; nt < 8; nt++)
#pragma unroll
        for (int r = 0; r < 4; r++) o_[nt][r] = 0.0f;

    const int aRowOff = w * 16 + (l & 15);
    const int aColOff = (l >> 4) << 3;
    const int bRowOff = (l & 7) + ((l >> 4) << 3);        // K (non-trans B)
    const int bColOff = ((l >> 3) & 1) << 3;
    const int vRowOff = (l & 7) + (((l >> 3) & 1) << 3);  // V (trans B): row = key
    const int vColOff = (l >> 4) << 3;                    //              col = dv

    for (int kt = 0; kt < 16; kt++) {
        const uint32_t cur = FKV0 + (uint32_t)(kt & 1) * KV_BUF;
        if (kt < 15) {
            cpKV((kt + 1) * 64, FKV0 + (uint32_t)((kt + 1) & 1) * KV_BUF);
            CP_COMMIT();
        }
        const uint32_t kvB = smB + 2u * cur;

        // ---- S = Q K^T, 3-term split
        float s[8][4];
#pragma unroll
        for (int nt = 0; nt < 8; nt++)
#pragma unroll
            for (int r = 0; r < 4; r++) s[nt][r] = 0.0f;
#pragma unroll
        for (int ks = 0; ks < 4; ks++) {
            const int k0 = ks * 16;
            uint32_t qh[4], ql[4], kh[4][4], kl[4][4];
            uint32_t offA = 2u * (uint32_t)(aRowOff * FST + k0 + aColOff);
            ldsm_x4(qh[0], qh[1], qh[2], qh[3], smB + (FQ_H * 2) + offA);
            ldsm_x4(ql[0], ql[1], ql[2], ql[3], smB + (FQ_L * 2) + offA);
#pragma unroll
            for (int g2 = 0; g2 < 4; g2++) {
                uint32_t offB = 2u * (uint32_t)((bRowOff + g2 * 16) * FST + k0 + bColOff);
                ldsm_x4(kh[g2][0], kh[g2][1], kh[g2][2], kh[g2][3], kvB + offB);
                ldsm_x4(kl[g2][0], kl[g2][1], kl[g2][2], kl[g2][3], kvB + 2u * KV_KL + offB);
            }
#pragma unroll
            for (int nt = 0; nt < 8; nt++) {
                const int g2 = nt >> 1, p = (nt & 1) * 2;
                mma_bf16(s[nt], qh, kh[g2][p], kh[g2][p + 1]);
                mma_bf16(s[nt], qh, kl[g2][p], kl[g2][p + 1]);
                mma_bf16(s[nt], ql, kh[g2][p], kh[g2][p + 1]);
            }
        }

        // ---- scale + online softmax (warp-local rows)
#pragma unroll
        for (int nt = 0; nt < 8; nt++)
#pragma unroll
            for (int r = 0; r < 4; r++) s[nt][r] *= SC;

#pragma unroll
        for (int hf = 0; hf < 2; hf++) {
            float mx = -1e30f;
#pragma unroll
            for (int nt = 0; nt < 8; nt++)
                mx = fmaxf(mx, fmaxf(s[nt][hf * 2], s[nt][hf * 2 + 1]));
            mx = fmaxf(mx, __shfl_xor_sync(0xffffffffu, mx, 1));
            mx = fmaxf(mx, __shfl_xor_sync(0xffffffffu, mx, 2));
            float mn = fmaxf(m_[hf], mx);
            float corr = exp2f(m_[hf] - mn);
            m_[hf] = mn;
            float rs = 0.0f;
#pragma unroll
            for (int nt = 0; nt < 8; nt++) {
                float p0 = exp2f(s[nt][hf * 2] - mn);
                float p1 = exp2f(s[nt][hf * 2 + 1] - mn);
                s[nt][hf * 2] = p0;
                s[nt][hf * 2 + 1] = p1;
                rs += p0 + p1;
            }
            rs += __shfl_xor_sync(0xffffffffu, rs, 1);
            rs += __shfl_xor_sync(0xffffffffu, rs, 2);
            l_[hf] = l_[hf] * corr + rs;
#pragma unroll
            for (int nt = 0; nt < 8; nt++) {
                o_[nt][hf * 2] *= corr;
                o_[nt][hf * 2 + 1] *= corr;
            }
        }

        // ---- O += P V (P from registers; V fragments via ldsm.trans)
#pragma unroll
        for (int ks = 0; ks < 4; ks++) {
            uint32_t pa_h[4], pa_l[4];
            pa_h[0] = pack_split(s[2 * ks][0], s[2 * ks][1], pa_l[0]);
            pa_h[1] = pack_split(s[2 * ks][2], s[2 * ks][3], pa_l[1]);
            pa_h[2] = pack_split(s[2 * ks + 1][0], s[2 * ks + 1][1], pa_l[2]);
            pa_h[3] = pack_split(s[2 * ks + 1][2], s[2 * ks + 1][3], pa_l[3]);
            const int k0 = ks * 16;
            uint32_t vh[4][4], vl[4][4];
#pragma unroll
            for (int g2 = 0; g2 < 4; g2++) {
                uint32_t offV =
                    2u * (uint32_t)((k0 + vRowOff) * FST + g2 * 16 + vColOff);
                ldsm_x4_t(vh[g2][0], vh[g2][1], vh[g2][2], vh[g2][3], kvB + 2u * KV_VH + offV);
                ldsm_x4_t(vl[g2][0], vl[g2][1], vl[g2][2], vl[g2][3], kvB + 2u * KV_VL + offV);
            }
#pragma unroll
            for (int nt = 0; nt < 8; nt++) {
                const int g2 = nt >> 1, p = (nt & 1) * 2;
                mma_bf16(o_[nt], pa_h, vh[g2][p], vh[g2][p + 1]);
                mma_bf16(o_[nt], pa_h, vl[g2][p], vl[g2][p + 1]);
                mma_bf16(o_[nt], pa_l, vh[g2][p], vh[g2][p + 1]);
            }
        }

        if (kt < 15) CP_WAIT0();
        __syncthreads();
    }

    // ---- normalize + store O as bf16 hi/lo (same split the GEMM would do)
    const float inv0 = 1.0f / l_[0];
    const float inv1 = 1.0f / l_[1];
    const int row = q0 + w * 16 + (l >> 2);
#pragma unroll
    for (int nt = 0; nt < 8; nt++) {
        int col = h * DHEAD + nt * 8 + 2 * (l & 3);
        long i0 = ((long)b * SEQ + row) * EMB + col;
        long i1 = ((long)b * SEQ + row + 8) * EMB + col;
        __nv_bfloat162 lo0, lo1;
        __nv_bfloat162 hi0 = split_hi(o_[nt][0] * inv0, o_[nt][1] * inv0, lo0);
        __nv_bfloat162 hi1 = split_hi(o_[nt][2] * inv1, o_[nt][3] * inv1, lo1);
        *(__nv_bfloat162*)(g_o_hi + i0) = hi0;
        *(__nv_bfloat162*)(g_o_lo + i0) = lo0;
        *(__nv_bfloat162*)(g_o_hi + i1) = hi1;
        *(__nv_bfloat162*)(g_o_lo + i1) = lo1;
    }
}

// ---------------- launch ---------------------------------------------------
extern "C" void kernel_launch(void* const* d_in, const int* in_sizes, int n_in,
                              void* d_out, int out_size) {
    const float* z    = (const float*)d_in[0];
    const float* Uqkv = (const float*)d_in[1];
    const float* Umsa = (const float*)d_in[2];
    float* out        = (float*)d_out;

    cudaFuncSetAttribute(flash_kernel, cudaFuncAttributeMaxDynamicSharedMemorySize, FLASH_SMEM);
    cudaFuncSetAttribute(hmma_gemm_kernel<QKVN, 1>,
                         cudaFuncAttributeMaxDynamicSharedMemorySize, GEMM_SMEM);
    cudaFuncSetAttribute(hmma_gemm_kernel<EMB, 2>,
                         cudaFuncAttributeMaxDynamicSharedMemorySize, GEMM_SMEM);

    pack_z_kernel<<<(NTOK * EMB / 2 + 255) / 256, 256>>>(z);
    pack_qkv_kernel<<<(QKVN * EMB + 255) / 256, 256>>>(Uqkv);
    pack_msa_kernel<<<(EMB * EMB + 255) / 256, 256>>>(Umsa);

    hmma_gemm_kernel<QKVN, 1><<<dim3(QKVN / 128, NTOK / 128), 256, GEMM_SMEM>>>(nullptr);

    flash_kernel<<<dim3(SEQ / 128, BATCH, NUM_HEAD), 256, FLASH_SMEM>>>();

    hmma_gemm_kernel<EMB, 2><<<dim3(EMB / 128, NTOK / 128), 256, GEMM_SMEM>>>(out);
}

// round 14
// speedup vs baseline: 1.0247x; 1.0247x over previous
#include <cuda_runtime.h>
#include <cuda_bf16.h>
#include <cstdint>

#define NUM_HEAD 12
#define BATCH    16
#define SEQ      1024
#define DHEAD    64
#define EMB      768
#define QKVN     2304   // 3 * 12 * 64
#define NTOK     (BATCH * SEQ)

// ======================= scratch (device globals) ==========================
__device__ __nv_bfloat16 g_z_hi[NTOK * EMB];                      // z split [tok][e]
__device__ __nv_bfloat16 g_z_lo[NTOK * EMB];
__device__ __nv_bfloat16 g_q_hi[NUM_HEAD * BATCH * SEQ * DHEAD];  // [h][b][n][d]
__device__ __nv_bfloat16 g_q_lo[NUM_HEAD * BATCH * SEQ * DHEAD];
__device__ __nv_bfloat16 g_k_hi[NUM_HEAD * BATCH * SEQ * DHEAD];
__device__ __nv_bfloat16 g_k_lo[NUM_HEAD * BATCH * SEQ * DHEAD];
__device__ __nv_bfloat16 g_v_hi[NUM_HEAD * BATCH * SEQ * DHEAD];
__device__ __nv_bfloat16 g_v_lo[NUM_HEAD * BATCH * SEQ * DHEAD];
__device__ __nv_bfloat16 g_o_hi[NTOK * EMB];                      // attn out split [tok][h*d]
__device__ __nv_bfloat16 g_o_lo[NTOK * EMB];
__device__ __nv_bfloat16 g_Wq_hi[QKVN * EMB];                     // QKV weights T [c][e]
__device__ __nv_bfloat16 g_Wq_lo[QKVN * EMB];
__device__ __nv_bfloat16 g_Wm_hi[EMB * EMB];                      // Umsa T [n][e]
__device__ __nv_bfloat16 g_Wm_lo[EMB * EMB];

// ======================= split helpers =====================================
__device__ __forceinline__ __nv_bfloat162 split_hi(float a, float b, __nv_bfloat162& lo) {
    __nv_bfloat162 hi;
    hi.x = __float2bfloat16(a);
    hi.y = __float2bfloat16(b);
    lo.x = __float2bfloat16(a - __bfloat162float(hi.x));
    lo.y = __float2bfloat16(b - __bfloat162float(hi.y));
    return hi;
}
__device__ __forceinline__ uint32_t pack_split(float a, float b, uint32_t& lo_u) {
    __nv_bfloat162 lo;
    __nv_bfloat162 hi = split_hi(a, b, lo);
    lo_u = *(uint32_t*)&lo;
    return *(uint32_t*)&hi;
}

// ---------------- packing kernels ------------------------------------------
__global__ void pack_z_kernel(const float* __restrict__ z) {
    int idx = blockIdx.x * blockDim.x + threadIdx.x;   // over NTOK*EMB/2
    if (idx >= NTOK * EMB / 2) return;
    float2 v = *(const float2*)(z + idx * 2);
    __nv_bfloat162 lo;
    __nv_bfloat162 hi = split_hi(v.x, v.y, lo);
    *(__nv_bfloat162*)(g_z_hi + idx * 2) = hi;
    *(__nv_bfloat162*)(g_z_lo + idx * 2) = lo;
}
__global__ void pack_qkv_kernel(const float* __restrict__ U) {
    int idx = blockIdx.x * blockDim.x + threadIdx.x;
    if (idx >= QKVN * EMB) return;
    int c = idx / EMB, e = idx - c * EMB;
    int h = c / 192, rem = c - h * 192;
    int r = rem >> 6, d = rem & 63;
    float v = U[((h * 3 + r) * EMB + e) * DHEAD + d];
    __nv_bfloat16 hi = __float2bfloat16(v);
    g_Wq_hi[idx] = hi;
    g_Wq_lo[idx] = __float2bfloat16(v - __bfloat162float(hi));
}
__global__ void pack_msa_kernel(const float* __restrict__ U) {
    int idx = blockIdx.x * blockDim.x + threadIdx.x;
    if (idx >= EMB * EMB) return;
    int n = idx / EMB, e = idx - n * EMB;
    float v = U[e * EMB + n];
    __nv_bfloat16 hi = __float2bfloat16(v);
    g_Wm_hi[idx] = hi;
    g_Wm_lo[idx] = __float2bfloat16(v - __bfloat162float(hi));
}

// ======================= warp-MMA / async helpers ==========================
__device__ __forceinline__ void ldsm_x4(uint32_t& r0, uint32_t& r1, uint32_t& r2, uint32_t& r3,
                                        uint32_t addr) {
    asm volatile("ldmatrix.sync.aligned.m8n8.x4.shared.b16 {%0,%1,%2,%3}, [%4];"
                 : "=r"(r0), "=r"(r1), "=r"(r2), "=r"(r3)
                 : "r"(addr));
}
__device__ __forceinline__ void ldsm_x4_t(uint32_t& r0, uint32_t& r1, uint32_t& r2, uint32_t& r3,
                                          uint32_t addr) {
    asm volatile("ldmatrix.sync.aligned.m8n8.x4.trans.shared.b16 {%0,%1,%2,%3}, [%4];"
                 : "=r"(r0), "=r"(r1), "=r"(r2), "=r"(r3)
                 : "r"(addr));
}
__device__ __forceinline__ void mma_bf16(float* c, const uint32_t* a, uint32_t b0, uint32_t b1) {
    asm volatile(
        "mma.sync.aligned.m16n8k16.row.col.f32.bf16.bf16.f32 "
        "{%0,%1,%2,%3}, {%4,%5,%6,%7}, {%8,%9}, {%0,%1,%2,%3};"
        : "+f"(c[0]), "+f"(c[1]), "+f"(c[2]), "+f"(c[3])
        : "r"(a[0]), "r"(a[1]), "r"(a[2]), "r"(a[3]), "r"(b0), "r"(b1));
}
__device__ __forceinline__ void cp_async16(uint32_t smem_addr, const void* gptr) {
    asm volatile("cp.async.cg.shared.global [%0], [%1], 16;" :: "r"(smem_addr), "l"(gptr));
}
#define CP_COMMIT() asm volatile("cp.async.commit_group;" ::: "memory")
#define CP_WAIT0()  asm volatile("cp.async.wait_group 0;" ::: "memory")

// ===== split-bf16 HMMA GEMM: C = A * B^T, 128x128 tile, all-async loads ====
// 256 thr, 8 warps (4m x 2n). Per-g2 B-fragment streaming to cut reg pressure.
#define AST   40
#define G_AH  0
#define G_AL  (128 * AST)
#define G_BH  (2 * 128 * AST)
#define G_BL  (3 * 128 * AST)
#define G_BUF (4 * 128 * AST)          // 20480 elems per buffer
#define GEMM_SMEM (2 * G_BUF * 2)      // 81920 bytes

template <int NC, int MODE>
__global__ void __launch_bounds__(256, 2) hmma_gemm_kernel(float* __restrict__ Cp) {
    extern __shared__ __nv_bfloat16 gsm[];
    const int t = threadIdx.x, w = t >> 5, l = t & 31;
    const int n0 = blockIdx.x * 128, m0 = blockIdx.y * 128;
    const int wm = w >> 1, wn = w & 1;

    const __nv_bfloat16* Ahg = (MODE == 1) ? g_z_hi : g_o_hi;
    const __nv_bfloat16* Alg = (MODE == 1) ? g_z_lo : g_o_lo;
    const __nv_bfloat16* Bhg = (MODE == 1) ? g_Wq_hi : g_Wm_hi;
    const __nv_bfloat16* Blg = (MODE == 1) ? g_Wq_lo : g_Wm_lo;

    float acc[2][8][4];
#pragma unroll
    for (int mt = 0; mt < 2; mt++)
#pragma unroll
        for (int nt = 0; nt < 8; nt++)
#pragma unroll
            for (int r = 0; r < 4; r++) acc[mt][nt][r] = 0.0f;

    const uint32_t smB = (uint32_t)__cvta_generic_to_shared(gsm);

    const int aRow = wm * 32 + (l & 15);            // + mt*16
    const int aCol = (l >> 4) << 3;
    const int bRowOff = (l & 7) + ((l >> 4) << 3);  // + wn*64 + g2*16
    const int bCol = ((l >> 3) & 1) << 3;

    const int prow = t >> 2, pc8 = (t & 3) << 3;    // tile loader: 64 rows/pass

    auto cpTiles = [&](int kc, uint32_t bufEl) {
#pragma unroll
        for (int i = 0; i < 2; i++) {
            int row = prow + i * 64;
            uint32_t off = 2u * (uint32_t)(row * AST + pc8);
            cp_async16(smB + 2u * (bufEl + G_AH) + off, Ahg + (long)(m0 + row) * 768 + kc + pc8);
            cp_async16(smB + 2u * (bufEl + G_AL) + off, Alg + (long)(m0 + row) * 768 + kc + pc8);
            cp_async16(smB + 2u * (bufEl + G_BH) + off, Bhg + (long)(n0 + row) * 768 + kc + pc8);
            cp_async16(smB + 2u * (bufEl + G_BL) + off, Blg + (long)(n0 + row) * 768 + kc + pc8);
        }
    };

    cpTiles(0, 0);
    CP_COMMIT();
    CP_WAIT0();
    __syncthreads();

    for (int c = 0; c < 24; c++) {
        const uint32_t cur = (uint32_t)(c & 1) * G_BUF;
        const uint32_t nxt = (uint32_t)((c + 1) & 1) * G_BUF;
        if (c < 23) {
            cpTiles((c + 1) * 32, nxt);
            CP_COMMIT();
        }

        const uint32_t aHB = smB + 2u * (cur + G_AH), aLB = smB + 2u * (cur + G_AL);
        const uint32_t bHB = smB + 2u * (cur + G_BH), bLB = smB + 2u * (cur + G_BL);
#pragma unroll
        for (int ks = 0; ks < 2; ks++) {
            const int k0 = ks * 16;
            uint32_t ah[2][4], al[2][4];
#pragma unroll
            for (int mt = 0; mt < 2; mt++) {
                uint32_t off = 2u * (uint32_t)((aRow + mt * 16) * AST + k0 + aCol);
                ldsm_x4(ah[mt][0], ah[mt][1], ah[mt][2], ah[mt][3], aHB + off);
                ldsm_x4(al[mt][0], al[mt][1], al[mt][2], al[mt][3], aLB + off);
            }
            // stream B fragments per g2: only 8 B-regs live at a time
#pragma unroll
            for (int g2 = 0; g2 < 4; g2++) {
                uint32_t bh[4], bl[4];
                uint32_t off =
                    2u * (uint32_t)((wn * 64 + g2 * 16 + bRowOff) * AST + k0 + bCol);
                ldsm_x4(bh[0], bh[1], bh[2], bh[3], bHB + off);
                ldsm_x4(bl[0], bl[1], bl[2], bl[3], bLB + off);
#pragma unroll
                for (int half = 0; half < 2; half++) {
                    const int nt = g2 * 2 + half, p = half * 2;
#pragma unroll
                    for (int mt = 0; mt < 2; mt++) {
                        mma_bf16(acc[mt][nt], ah[mt], bh[p], bh[p + 1]);
                        mma_bf16(acc[mt][nt], ah[mt], bl[p], bl[p + 1]);
                        mma_bf16(acc[mt][nt], al[mt], bh[p], bh[p + 1]);
                    }
                }
            }
        }

        if (c < 23) CP_WAIT0();
        __syncthreads();
    }

    // ---- epilogue
    const int rBase = m0 + wm * 32 + (l >> 2);
    const int cBase = wn * 64 + 2 * (l & 3);
    if (MODE == 2) {
#pragma unroll
        for (int mt = 0; mt < 2; mt++)
#pragma unroll
            for (int nt = 0; nt < 8; nt++) {
                int rA = rBase + mt * 16;
                int c = n0 + cBase + nt * 8;
                *(float2*)(Cp + (long)rA * NC + c) = make_float2(acc[mt][nt][0], acc[mt][nt][1]);
                *(float2*)(Cp + (long)(rA + 8) * NC + c) =
                    make_float2(acc[mt][nt][2], acc[mt][nt][3]);
            }
    } else {
        // QKV epilogue: q/k/v in natural [h][b][n][d] bf16 hi/lo
        const int g = (n0 + wn * 64) >> 6;  // h*3 + r
        const int h = g / 3, r = g - h * 3;
        __nv_bfloat16* dh = (r == 0 ? g_q_hi : (r == 1 ? g_k_hi : g_v_hi));
        __nv_bfloat16* dl = (r == 0 ? g_q_lo : (r == 1 ? g_k_lo : g_v_lo));
#pragma unroll
        for (int mt = 0; mt < 2; mt++) {
            int m = rBase + mt * 16;
            int b = m >> 10, tok = m & 1023;
            int hb = h * BATCH + b;
#pragma unroll
            for (int nt = 0; nt < 8; nt++) {
                int d = 2 * (l & 3) + nt * 8;
                long i0 = ((long)hb * SEQ + tok) * DHEAD + d;
                __nv_bfloat162 lo01, lo23;
                __nv_bfloat162 hi01 = split_hi(acc[mt][nt][0], acc[mt][nt][1], lo01);
                __nv_bfloat162 hi23 = split_hi(acc[mt][nt][2], acc[mt][nt][3], lo23);
                *(__nv_bfloat162*)(dh + i0) = hi01;
                *(__nv_bfloat162*)(dl + i0) = lo01;
                *(__nv_bfloat162*)(dh + i0 + 8 * DHEAD) = hi23;
                *(__nv_bfloat162*)(dl + i0 + 8 * DHEAD) = lo23;
            }
        }
    }
}

// ========= flash attention: FA2 + cp.async; per-g2 fragment streaming ======
#define FST 72
#define FQ_H 0
#define FQ_L (128 * FST)
#define FKV0 (2 * 128 * FST)
#define KV_KL (64 * FST)
#define KV_VH (2 * 64 * FST)
#define KV_VL (3 * 64 * FST)
#define KV_BUF (4 * 64 * FST)
#define FLASH_SMEM ((2 * 128 * FST + 2 * KV_BUF) * 2)   // 110592 bytes

__global__ void __launch_bounds__(256, 2) flash_kernel() {
    extern __shared__ __nv_bfloat16 sm[];
    const int t = threadIdx.x, w = t >> 5, l = t & 31;
    const int h = blockIdx.z, b = blockIdx.y, q0 = blockIdx.x * 128;
    const int hb = h * BATCH + b;
    const float SC = 0.125f * 1.4426950408889634f;

    const __nv_bfloat16* Qh = g_q_hi + ((long)hb * SEQ + q0) * DHEAD;
    const __nv_bfloat16* Ql = g_q_lo + ((long)hb * SEQ + q0) * DHEAD;
    const __nv_bfloat16* Kh = g_k_hi + (long)hb * SEQ * DHEAD;
    const __nv_bfloat16* Kl = g_k_lo + (long)hb * SEQ * DHEAD;
    const __nv_bfloat16* Vh = g_v_hi + (long)hb * SEQ * DHEAD;
    const __nv_bfloat16* Vl = g_v_lo + (long)hb * SEQ * DHEAD;

    const uint32_t smB = (uint32_t)__cvta_generic_to_shared(sm);
    const int lrow = t >> 3, lc8 = (t & 7) << 3;

    auto cpKV = [&](int kb, uint32_t bufEl) {
#pragma unroll
        for (int i = 0; i < 2; i++) {
            int row = lrow + i * 32;
            uint32_t off = 2u * (uint32_t)(row * FST + lc8);
            cp_async16(smB + 2u * bufEl + off, Kh + (long)(kb + row) * DHEAD + lc8);
            cp_async16(smB + 2u * (bufEl + KV_KL) + off, Kl + (long)(kb + row) * DHEAD + lc8);
            cp_async16(smB + 2u * (bufEl + KV_VH) + off, Vh + (long)(kb + row) * DHEAD + lc8);
            cp_async16(smB + 2u * (bufEl + KV_VL) + off, Vl + (long)(kb + row) * DHEAD + lc8);
        }
    };

    cpKV(0, FKV0);
    CP_COMMIT();
#pragma unroll
    for (int i = 0; i < 4; i++) {
        int idx = t + i * 256;
        int row = idx >> 3, c8 = (idx & 7) << 3;
        *(uint4*)&sm[FQ_H + row * FST + c8] = *(const uint4*)(Qh + row * DHEAD + c8);
        *(uint4*)&sm[FQ_L + row * FST + c8] = *(const uint4*)(Ql + row * DHEAD + c8);
    }
    CP_WAIT0();
    __syncthreads();

    float m_[2], l_[2], o_[8][4];
    m_[0] = m_[1] = -1e30f;
    l_[0] = l_[1] = 0.0f;
#pragma unroll
    for (int nt = 0; nt < 8; nt++)
#pragma unroll
        for (int r = 0; r < 4; r++) o_[nt][r] = 0.0f;

    const int aRowOff = w * 16 + (l & 15);
    const int aColOff = (l >> 4) << 3;
    const int bRowOff = (l & 7) + ((l >> 4) << 3);        // K (non-trans B)
    const int bColOff = ((l >> 3) & 1) << 3;
    const int vRowOff = (l & 7) + (((l >> 3) & 1) << 3);  // V (trans B): row = key
    const int vColOff = (l >> 4) << 3;                    //              col = dv

    for (int kt = 0; kt < 16; kt++) {
        const uint32_t cur = FKV0 + (uint32_t)(kt & 1) * KV_BUF;
        if (kt < 15) {
            cpKV((kt + 1) * 64, FKV0 + (uint32_t)((kt + 1) & 1) * KV_BUF);
            CP_COMMIT();
        }
        const uint32_t kvB = smB + 2u * cur;

        // ---- S = Q K^T, 3-term split, K frags streamed per g2
        float s[8][4];
#pragma unroll
        for (int nt = 0; nt < 8; nt++)
#pragma unroll
            for (int r = 0; r < 4; r++) s[nt][r] = 0.0f;
#pragma unroll
        for (int ks = 0; ks < 4; ks++) {
            const int k0 = ks * 16;
            uint32_t qh[4], ql[4];
            uint32_t offA = 2u * (uint32_t)(aRowOff * FST + k0 + aColOff);
            ldsm_x4(qh[0], qh[1], qh[2], qh[3], smB + (FQ_H * 2) + offA);
            ldsm_x4(ql[0], ql[1], ql[2], ql[3], smB + (FQ_L * 2) + offA);
#pragma unroll
            for (int g2 = 0; g2 < 4; g2++) {
                uint32_t kh[4], kl[4];
                uint32_t offB = 2u * (uint32_t)((bRowOff + g2 * 16) * FST + k0 + bColOff);
                ldsm_x4(kh[0], kh[1], kh[2], kh[3], kvB + offB);
                ldsm_x4(kl[0], kl[1], kl[2], kl[3], kvB + 2u * KV_KL + offB);
#pragma unroll
                for (int half = 0; half < 2; half++) {
                    const int nt = g2 * 2 + half, p = half * 2;
                    mma_bf16(s[nt], qh, kh[p], kh[p + 1]);
                    mma_bf16(s[nt], qh, kl[p], kl[p + 1]);
                    mma_bf16(s[nt], ql, kh[p], kh[p + 1]);
                }
            }
        }

        // ---- scale + online softmax (warp-local rows)
#pragma unroll
        for (int nt = 0; nt < 8; nt++)
#pragma unroll
            for (int r = 0; r < 4; r++) s[nt][r] *= SC;

#pragma unroll
        for (int hf = 0; hf < 2; hf++) {
            float mx = -1e30f;
#pragma unroll
            for (int nt = 0; nt < 8; nt++)
                mx = fmaxf(mx, fmaxf(s[nt][hf * 2], s[nt][hf * 2 + 1]));
            mx = fmaxf(mx, __shfl_xor_sync(0xffffffffu, mx, 1));
            mx = fmaxf(mx, __shfl_xor_sync(0xffffffffu, mx, 2));
            float mn = fmaxf(m_[hf], mx);
            float corr = exp2f(m_[hf] - mn);
            m_[hf] = mn;
            float rs = 0.0f;
#pragma unroll
            for (int nt = 0; nt < 8; nt++) {
                float p0 = exp2f(s[nt][hf * 2] - mn);
                float p1 = exp2f(s[nt][hf * 2 + 1] - mn);
                s[nt][hf * 2] = p0;
                s[nt][hf * 2 + 1] = p1;
                rs += p0 + p1;
            }
            rs += __shfl_xor_sync(0xffffffffu, rs, 1);
            rs += __shfl_xor_sync(0xffffffffu, rs, 2);
            l_[hf] = l_[hf] * corr + rs;
#pragma unroll
            for (int nt = 0; nt < 8; nt++) {
                o_[nt][hf * 2] *= corr;
                o_[nt][hf * 2 + 1] *= corr;
            }
        }

        // ---- O += P V (P from registers; V frags streamed per g2)
#pragma unroll
        for (int ks = 0; ks < 4; ks++) {
            uint32_t pa_h[4], pa_l[4];
            pa_h[0] = pack_split(s[2 * ks][0], s[2 * ks][1], pa_l[0]);
            pa_h[1] = pack_split(s[2 * ks][2], s[2 * ks][3], pa_l[1]);
            pa_h[2] = pack_split(s[2 * ks + 1][0], s[2 * ks + 1][1], pa_l[2]);
            pa_h[3] = pack_split(s[2 * ks + 1][2], s[2 * ks + 1][3], pa_l[3]);
            const int k0 = ks * 16;
#pragma unroll
            for (int g2 = 0; g2 < 4; g2++) {
                uint32_t vh[4], vl[4];
                uint32_t offV =
                    2u * (uint32_t)((k0 + vRowOff) * FST + g2 * 16 + vColOff);
                ldsm_x4_t(vh[0], vh[1], vh[2], vh[3], kvB + 2u * KV_VH + offV);
                ldsm_x4_t(vl[0], vl[1], vl[2], vl[3], kvB + 2u * KV_VL + offV);
#pragma unroll
                for (int half = 0; half < 2; half++) {
                    const int nt = g2 * 2 + half, p = half * 2;
                    mma_bf16(o_[nt], pa_h, vh[p], vh[p + 1]);
                    mma_bf16(o_[nt], pa_h, vl[p], vl[p + 1]);
                    mma_bf16(o_[nt], pa_l, vh[p], vh[p + 1]);
                }
            }
        }

        if (kt < 15) CP_WAIT0();
        __syncthreads();
    }

    // ---- normalize + store O as bf16 hi/lo (same split the GEMM would do)
    const float inv0 = 1.0f / l_[0];
    const float inv1 = 1.0f / l_[1];
    const int row = q0 + w * 16 + (l >> 2);
#pragma unroll
    for (int nt = 0; nt < 8; nt++) {
        int col = h * DHEAD + nt * 8 + 2 * (l & 3);
        long i0 = ((long)b * SEQ + row) * EMB + col;
        long i1 = ((long)b * SEQ + row + 8) * EMB + col;
        __nv_bfloat162 lo0, lo1;
        __nv_bfloat162 hi0 = split_hi(o_[nt][0] * inv0, o_[nt][1] * inv0, lo0);
        __nv_bfloat162 hi1 = split_hi(o_[nt][2] * inv1, o_[nt][3] * inv1, lo1);
        *(__nv_bfloat162*)(g_o_hi + i0) = hi0;
        *(__nv_bfloat162*)(g_o_lo + i0) = lo0;
        *(__nv_bfloat162*)(g_o_hi + i1) = hi1;
        *(__nv_bfloat162*)(g_o_lo + i1) = lo1;
    }
}

// ---------------- launch ---------------------------------------------------
extern "C" void kernel_launch(void* const* d_in, const int* in_sizes, int n_in,
                              void* d_out, int out_size) {
    const float* z    = (const float*)d_in[0];
    const float* Uqkv = (const float*)d_in[1];
    const float* Umsa = (const float*)d_in[2];
    float* out        = (float*)d_out;

    cudaFuncSetAttribute(flash_kernel, cudaFuncAttributeMaxDynamicSharedMemorySize, FLASH_SMEM);
    cudaFuncSetAttribute(hmma_gemm_kernel<QKVN, 1>,
                         cudaFuncAttributeMaxDynamicSharedMemorySize, GEMM_SMEM);
    cudaFuncSetAttribute(hmma_gemm_kernel<EMB, 2>,
                         cudaFuncAttributeMaxDynamicSharedMemorySize, GEMM_SMEM);

    pack_z_kernel<<<(NTOK * EMB / 2 + 255) / 256, 256>>>(z);
    pack_qkv_kernel<<<(QKVN * EMB + 255) / 256, 256>>>(Uqkv);
    pack_msa_kernel<<<(EMB * EMB + 255) / 256, 256>>>(Umsa);

    hmma_gemm_kernel<QKVN, 1><<<dim3(QKVN / 128, NTOK / 128), 256, GEMM_SMEM>>>(nullptr);

    flash_kernel<<<dim3(SEQ / 128, BATCH, NUM_HEAD), 256, FLASH_SMEM>>>();

    hmma_gemm_kernel<EMB, 2><<<dim3(EMB / 128, NTOK / 128), 256, GEMM_SMEM>>>(out);
}

// round 16
// speedup vs baseline: 1.0249x; 1.0003x over previous
#include <cuda_runtime.h>
#include <cuda_bf16.h>
#include <cstdint>

#define NUM_HEAD 12
#define BATCH    16
#define SEQ      1024
#define DHEAD    64
#define EMB      768
#define QKVN     2304   // 3 * 12 * 64
#define NTOK     (BATCH * SEQ)

// ======================= scratch (device globals) ==========================
__device__ __nv_bfloat16 g_z_hi[NTOK * EMB];                      // z split [tok][e]
__device__ __nv_bfloat16 g_z_lo[NTOK * EMB];
__device__ __nv_bfloat16 g_q_hi[NUM_HEAD * BATCH * SEQ * DHEAD];  // [h][b][n][d]
__device__ __nv_bfloat16 g_q_lo[NUM_HEAD * BATCH * SEQ * DHEAD];
__device__ __nv_bfloat16 g_k_hi[NUM_HEAD * BATCH * SEQ * DHEAD];
__device__ __nv_bfloat16 g_k_lo[NUM_HEAD * BATCH * SEQ * DHEAD];
__device__ __nv_bfloat16 g_v_hi[NUM_HEAD * BATCH * SEQ * DHEAD];
__device__ __nv_bfloat16 g_v_lo[NUM_HEAD * BATCH * SEQ * DHEAD];
__device__ __nv_bfloat16 g_o_hi[NTOK * EMB];                      // attn out split [tok][h*d]
__device__ __nv_bfloat16 g_o_lo[NTOK * EMB];
__device__ __nv_bfloat16 g_Wq_hi[QKVN * EMB];                     // QKV weights T [c][e]
__device__ __nv_bfloat16 g_Wq_lo[QKVN * EMB];
__device__ __nv_bfloat16 g_Wm_hi[EMB * EMB];                      // Umsa T [n][e]
__device__ __nv_bfloat16 g_Wm_lo[EMB * EMB];

// ======================= split helpers =====================================
__device__ __forceinline__ __nv_bfloat162 split_hi(float a, float b, __nv_bfloat162& lo) {
    __nv_bfloat162 hi;
    hi.x = __float2bfloat16(a);
    hi.y = __float2bfloat16(b);
    lo.x = __float2bfloat16(a - __bfloat162float(hi.x));
    lo.y = __float2bfloat16(b - __bfloat162float(hi.y));
    return hi;
}
__device__ __forceinline__ uint32_t pack_split(float a, float b, uint32_t& lo_u) {
    __nv_bfloat162 lo;
    __nv_bfloat162 hi = split_hi(a, b, lo);
    lo_u = *(uint32_t*)&lo;
    return *(uint32_t*)&hi;
}

// ---------------- packing kernels ------------------------------------------
__global__ void pack_z_kernel(const float* __restrict__ z) {
    int idx = blockIdx.x * blockDim.x + threadIdx.x;   // over NTOK*EMB/2
    if (idx >= NTOK * EMB / 2) return;
    float2 v = *(const float2*)(z + idx * 2);
    __nv_bfloat162 lo;
    __nv_bfloat162 hi = split_hi(v.x, v.y, lo);
    *(__nv_bfloat162*)(g_z_hi + idx * 2) = hi;
    *(__nv_bfloat162*)(g_z_lo + idx * 2) = lo;
}
__global__ void pack_qkv_kernel(const float* __restrict__ U) {
    int idx = blockIdx.x * blockDim.x + threadIdx.x;
    if (idx >= QKVN * EMB) return;
    int c = idx / EMB, e = idx - c * EMB;
    int h = c / 192, rem = c - h * 192;
    int r = rem >> 6, d = rem & 63;
    float v = U[((h * 3 + r) * EMB + e) * DHEAD + d];
    __nv_bfloat16 hi = __float2bfloat16(v);
    g_Wq_hi[idx] = hi;
    g_Wq_lo[idx] = __float2bfloat16(v - __bfloat162float(hi));
}
__global__ void pack_msa_kernel(const float* __restrict__ U) {
    int idx = blockIdx.x * blockDim.x + threadIdx.x;
    if (idx >= EMB * EMB) return;
    int n = idx / EMB, e = idx - n * EMB;
    float v = U[e * EMB + n];
    __nv_bfloat16 hi = __float2bfloat16(v);
    g_Wm_hi[idx] = hi;
    g_Wm_lo[idx] = __float2bfloat16(v - __bfloat162float(hi));
}

// ======================= warp-MMA / async helpers ==========================
__device__ __forceinline__ void ldsm_x4(uint32_t& r0, uint32_t& r1, uint32_t& r2, uint32_t& r3,
                                        uint32_t addr) {
    asm volatile("ldmatrix.sync.aligned.m8n8.x4.shared.b16 {%0,%1,%2,%3}, [%4];"
                 : "=r"(r0), "=r"(r1), "=r"(r2), "=r"(r3)
                 : "r"(addr));
}
__device__ __forceinline__ void ldsm_x4_t(uint32_t& r0, uint32_t& r1, uint32_t& r2, uint32_t& r3,
                                          uint32_t addr) {
    asm volatile("ldmatrix.sync.aligned.m8n8.x4.trans.shared.b16 {%0,%1,%2,%3}, [%4];"
                 : "=r"(r0), "=r"(r1), "=r"(r2), "=r"(r3)
                 : "r"(addr));
}
__device__ __forceinline__ void mma_bf16(float* c, const uint32_t* a, uint32_t b0, uint32_t b1) {
    asm volatile(
        "mma.sync.aligned.m16n8k16.row.col.f32.bf16.bf16.f32 "
        "{%0,%1,%2,%3}, {%4,%5,%6,%7}, {%8,%9}, {%0,%1,%2,%3};"
        : "+f"(c[0]), "+f"(c[1]), "+f"(c[2]), "+f"(c[3])
        : "r"(a[0]), "r"(a[1]), "r"(a[2]), "r"(a[3]), "r"(b0), "r"(b1));
}
__device__ __forceinline__ void cp_async16(uint32_t smem_addr, const void* gptr) {
    asm volatile("cp.async.cg.shared.global [%0], [%1], 16;" :: "r"(smem_addr), "l"(gptr));
}
#define CP_COMMIT() asm volatile("cp.async.commit_group;" ::: "memory")
#define CP_WAIT0()  asm volatile("cp.async.wait_group 0;" ::: "memory")

// ===== split-bf16 HMMA GEMM: C = A * B^T, 128x128 tile, all-async loads ====
// 256 thr, 8 warps (4m x 2n). Term-major MMA order: same-acc updates spaced 4.
#define AST   40
#define G_AH  0
#define G_AL  (128 * AST)
#define G_BH  (2 * 128 * AST)
#define G_BL  (3 * 128 * AST)
#define G_BUF (4 * 128 * AST)          // 20480 elems per buffer
#define GEMM_SMEM (2 * G_BUF * 2)      // 81920 bytes

template <int NC, int MODE>
__global__ void __launch_bounds__(256, 2) hmma_gemm_kernel(float* __restrict__ Cp) {
    extern __shared__ __nv_bfloat16 gsm[];
    const int t = threadIdx.x, w = t >> 5, l = t & 31;
    const int n0 = blockIdx.x * 128, m0 = blockIdx.y * 128;
    const int wm = w >> 1, wn = w & 1;

    const __nv_bfloat16* Ahg = (MODE == 1) ? g_z_hi : g_o_hi;
    const __nv_bfloat16* Alg = (MODE == 1) ? g_z_lo : g_o_lo;
    const __nv_bfloat16* Bhg = (MODE == 1) ? g_Wq_hi : g_Wm_hi;
    const __nv_bfloat16* Blg = (MODE == 1) ? g_Wq_lo : g_Wm_lo;

    float acc[2][8][4];
#pragma unroll
    for (int mt = 0; mt < 2; mt++)
#pragma unroll
        for (int nt = 0; nt < 8; nt++)
#pragma unroll
            for (int r = 0; r < 4; r++) acc[mt][nt][r] = 0.0f;

    const uint32_t smB = (uint32_t)__cvta_generic_to_shared(gsm);

    const int aRow = wm * 32 + (l & 15);            // + mt*16
    const int aCol = (l >> 4) << 3;
    const int bRowOff = (l & 7) + ((l >> 4) << 3);  // + wn*64 + g2*16
    const int bCol = ((l >> 3) & 1) << 3;

    const int prow = t >> 2, pc8 = (t & 3) << 3;    // tile loader: 64 rows/pass

    auto cpTiles = [&](int kc, uint32_t bufEl) {
#pragma unroll
        for (int i = 0; i < 2; i++) {
            int row = prow + i * 64;
            uint32_t off = 2u * (uint32_t)(row * AST + pc8);
            cp_async16(smB + 2u * (bufEl + G_AH) + off, Ahg + (long)(m0 + row) * 768 + kc + pc8);
            cp_async16(smB + 2u * (bufEl + G_AL) + off, Alg + (long)(m0 + row) * 768 + kc + pc8);
            cp_async16(smB + 2u * (bufEl + G_BH) + off, Bhg + (long)(n0 + row) * 768 + kc + pc8);
            cp_async16(smB + 2u * (bufEl + G_BL) + off, Blg + (long)(n0 + row) * 768 + kc + pc8);
        }
    };

    cpTiles(0, 0);
    CP_COMMIT();
    CP_WAIT0();
    __syncthreads();

    for (int c = 0; c < 24; c++) {
        const uint32_t cur = (uint32_t)(c & 1) * G_BUF;
        const uint32_t nxt = (uint32_t)((c + 1) & 1) * G_BUF;
        if (c < 23) {
            cpTiles((c + 1) * 32, nxt);
            CP_COMMIT();
        }

        const uint32_t aHB = smB + 2u * (cur + G_AH), aLB = smB + 2u * (cur + G_AL);
        const uint32_t bHB = smB + 2u * (cur + G_BH), bLB = smB + 2u * (cur + G_BL);
#pragma unroll
        for (int ks = 0; ks < 2; ks++) {
            const int k0 = ks * 16;
            uint32_t ah[2][4], al[2][4];
#pragma unroll
            for (int mt = 0; mt < 2; mt++) {
                uint32_t off = 2u * (uint32_t)((aRow + mt * 16) * AST + k0 + aCol);
                ldsm_x4(ah[mt][0], ah[mt][1], ah[mt][2], ah[mt][3], aHB + off);
                ldsm_x4(al[mt][0], al[mt][1], al[mt][2], al[mt][3], aLB + off);
            }
#pragma unroll
            for (int g2 = 0; g2 < 4; g2++) {
                uint32_t bh[4], bl[4];
                uint32_t off =
                    2u * (uint32_t)((wn * 64 + g2 * 16 + bRowOff) * AST + k0 + bCol);
                ldsm_x4(bh[0], bh[1], bh[2], bh[3], bHB + off);
                ldsm_x4(bl[0], bl[1], bl[2], bl[3], bLB + off);
                // term-major: same-acc updates spaced 4 apart (latency hiding)
#pragma unroll
                for (int term = 0; term < 3; term++)
#pragma unroll
                    for (int half = 0; half < 2; half++)
#pragma unroll
                        for (int mt = 0; mt < 2; mt++) {
                            const int nt = g2 * 2 + half, p = half * 2;
                            if (term == 0)
                                mma_bf16(acc[mt][nt], ah[mt], bh[p], bh[p + 1]);
                            else if (term == 1)
                                mma_bf16(acc[mt][nt], ah[mt], bl[p], bl[p + 1]);
                            else
                                mma_bf16(acc[mt][nt], al[mt], bh[p], bh[p + 1]);
                        }
            }
        }

        if (c < 23) CP_WAIT0();
        __syncthreads();
    }

    // ---- epilogue
    const int rBase = m0 + wm * 32 + (l >> 2);
    const int cBase = wn * 64 + 2 * (l & 3);
    if (MODE == 2) {
#pragma unroll
        for (int mt = 0; mt < 2; mt++)
#pragma unroll
            for (int nt = 0; nt < 8; nt++) {
                int rA = rBase + mt * 16;
                int c = n0 + cBase + nt * 8;
                *(float2*)(Cp + (long)rA * NC + c) = make_float2(acc[mt][nt][0], acc[mt][nt][1]);
                *(float2*)(Cp + (long)(rA + 8) * NC + c) =
                    make_float2(acc[mt][nt][2], acc[mt][nt][3]);
            }
    } else {
        // QKV epilogue: q/k/v in natural [h][b][n][d] bf16 hi/lo
        const int g = (n0 + wn * 64) >> 6;  // h*3 + r
        const int h = g / 3, r = g - h * 3;
        __nv_bfloat16* dh = (r == 0 ? g_q_hi : (r == 1 ? g_k_hi : g_v_hi));
        __nv_bfloat16* dl = (r == 0 ? g_q_lo : (r == 1 ? g_k_lo : g_v_lo));
#pragma unroll
        for (int mt = 0; mt < 2; mt++) {
            int m = rBase + mt * 16;
            int b = m >> 10, tok = m & 1023;
            int hb = h * BATCH + b;
#pragma unroll
            for (int nt = 0; nt < 8; nt++) {
                int d = 2 * (l & 3) + nt * 8;
                long i0 = ((long)hb * SEQ + tok) * DHEAD + d;
                __nv_bfloat162 lo01, lo23;
                __nv_bfloat162 hi01 = split_hi(acc[mt][nt][0], acc[mt][nt][1], lo01);
                __nv_bfloat162 hi23 = split_hi(acc[mt][nt][2], acc[mt][nt][3], lo23);
                *(__nv_bfloat162*)(dh + i0) = hi01;
                *(__nv_bfloat162*)(dl + i0) = lo01;
                *(__nv_bfloat162*)(dh + i0 + 8 * DHEAD) = hi23;
                *(__nv_bfloat162*)(dl + i0 + 8 * DHEAD) = lo23;
            }
        }
    }
}

// ========= flash attention: FA2 + cp.async; g2-pair term-major MMAs ========
#define FST 72
#define FQ_H 0
#define FQ_L (128 * FST)
#define FKV0 (2 * 128 * FST)
#define KV_KL (64 * FST)
#define KV_VH (2 * 64 * FST)
#define KV_VL (3 * 64 * FST)
#define KV_BUF (4 * 64 * FST)
#define FLASH_SMEM ((2 * 128 * FST + 2 * KV_BUF) * 2)   // 110592 bytes

__global__ void __launch_bounds__(256, 2) flash_kernel() {
    extern __shared__ __nv_bfloat16 sm[];
    const int t = threadIdx.x, w = t >> 5, l = t & 31;
    const int h = blockIdx.z, b = blockIdx.y, q0 = blockIdx.x * 128;
    const int hb = h * BATCH + b;
    const float SC = 0.125f * 1.4426950408889634f;

    const __nv_bfloat16* Qh = g_q_hi + ((long)hb * SEQ + q0) * DHEAD;
    const __nv_bfloat16* Ql = g_q_lo + ((long)hb * SEQ + q0) * DHEAD;
    const __nv_bfloat16* Kh = g_k_hi + (long)hb * SEQ * DHEAD;
    const __nv_bfloat16* Kl = g_k_lo + (long)hb * SEQ * DHEAD;
    const __nv_bfloat16* Vh = g_v_hi + (long)hb * SEQ * DHEAD;
    const __nv_bfloat16* Vl = g_v_lo + (long)hb * SEQ * DHEAD;

    const uint32_t smB = (uint32_t)__cvta_generic_to_shared(sm);
    const int lrow = t >> 3, lc8 = (t & 7) << 3;

    auto cpKV = [&](int kb, uint32_t bufEl) {
#pragma unroll
        for (int i = 0; i < 2; i++) {
            int row = lrow + i * 32;
            uint32_t off = 2u * (uint32_t)(row * FST + lc8);
            cp_async16(smB + 2u * bufEl + off, Kh + (long)(kb + row) * DHEAD + lc8);
            cp_async16(smB + 2u * (bufEl + KV_KL) + off, Kl + (long)(kb + row) * DHEAD + lc8);
            cp_async16(smB + 2u * (bufEl + KV_VH) + off, Vh + (long)(kb + row) * DHEAD + lc8);
            cp_async16(smB + 2u * (bufEl + KV_VL) + off, Vl + (long)(kb + row) * DHEAD + lc8);
        }
    };

    cpKV(0, FKV0);
    CP_COMMIT();
#pragma unroll
    for (int i = 0; i < 4; i++) {
        int idx = t + i * 256;
        int row = idx >> 3, c8 = (idx & 7) << 3;
        *(uint4*)&sm[FQ_H + row * FST + c8] = *(const uint4*)(Qh + row * DHEAD + c8);
        *(uint4*)&sm[FQ_L + row * FST + c8] = *(const uint4*)(Ql + row * DHEAD + c8);
    }
    CP_WAIT0();
    __syncthreads();

    float m_[2], l_[2], o_[8][4];
    m_[0] = m_[1] = -1e30f;
    l_[0] = l_[1] = 0.0f;
#pragma unroll
    for (int nt = 0; nt < 8; nt++)
#pragma unroll
        for (int r = 0; r < 4; r++) o_[nt][r] = 0.0f;

    const int aRowOff = w * 16 + (l & 15);
    const int aColOff = (l >> 4) << 3;
    const int bRowOff = (l & 7) + ((l >> 4) << 3);        // K (non-trans B)
    const int bColOff = ((l >> 3) & 1) << 3;
    const int vRowOff = (l & 7) + (((l >> 3) & 1) << 3);  // V (trans B): row = key
    const int vColOff = (l >> 4) << 3;                    //              col = dv

    for (int kt = 0; kt < 16; kt++) {
        const uint32_t cur = FKV0 + (uint32_t)(kt & 1) * KV_BUF;
        if (kt < 15) {
            cpKV((kt + 1) * 64, FKV0 + (uint32_t)((kt + 1) & 1) * KV_BUF);
            CP_COMMIT();
        }
        const uint32_t kvB = smB + 2u * cur;

        // ---- S = Q K^T, 3-term split, g2-pair + term-major (spacing 4)
        float s[8][4];
#pragma unroll
        for (int nt = 0; nt < 8; nt++)
#pragma unroll
            for (int r = 0; r < 4; r++) s[nt][r] = 0.0f;
#pragma unroll
        for (int ks = 0; ks < 4; ks++) {
            const int k0 = ks * 16;
            uint32_t qh[4], ql[4];
            uint32_t offA = 2u * (uint32_t)(aRowOff * FST + k0 + aColOff);
            ldsm_x4(qh[0], qh[1], qh[2], qh[3], smB + (FQ_H * 2) + offA);
            ldsm_x4(ql[0], ql[1], ql[2], ql[3], smB + (FQ_L * 2) + offA);
#pragma unroll
            for (int g2p = 0; g2p < 2; g2p++) {
                uint32_t kh[2][4], kl[2][4];
#pragma unroll
                for (int j = 0; j < 2; j++) {
                    uint32_t offB = 2u * (uint32_t)((bRowOff + (g2p * 2 + j) * 16) * FST +
                                                    k0 + bColOff);
                    ldsm_x4(kh[j][0], kh[j][1], kh[j][2], kh[j][3], kvB + offB);
                    ldsm_x4(kl[j][0], kl[j][1], kl[j][2], kl[j][3], kvB + 2u * KV_KL + offB);
                }
#pragma unroll
                for (int term = 0; term < 3; term++)
#pragma unroll
                    for (int j = 0; j < 2; j++)
#pragma unroll
                        for (int half = 0; half < 2; half++) {
                            const int nt = (g2p * 2 + j) * 2 + half, p = half * 2;
                            if (term == 0)
                                mma_bf16(s[nt], qh, kh[j][p], kh[j][p + 1]);
                            else if (term == 1)
                                mma_bf16(s[nt], qh, kl[j][p], kl[j][p + 1]);
                            else
                                mma_bf16(s[nt], ql, kh[j][p], kh[j][p + 1]);
                        }
            }
        }

        // ---- scale + online softmax (warp-local rows)
#pragma unroll
        for (int nt = 0; nt < 8; nt++)
#pragma unroll
            for (int r = 0; r < 4; r++) s[nt][r] *= SC;

#pragma unroll
        for (int hf = 0; hf < 2; hf++) {
            float mx = -1e30f;
#pragma unroll
            for (int nt = 0; nt < 8; nt++)
                mx = fmaxf(mx, fmaxf(s[nt][hf * 2], s[nt][hf * 2 + 1]));
            mx = fmaxf(mx, __shfl_xor_sync(0xffffffffu, mx, 1));
            mx = fmaxf(mx, __shfl_xor_sync(0xffffffffu, mx, 2));
            float mn = fmaxf(m_[hf], mx);
            float corr = exp2f(m_[hf] - mn);
            m_[hf] = mn;
            float rs = 0.0f;
#pragma unroll
            for (int nt = 0; nt < 8; nt++) {
                float p0 = exp2f(s[nt][hf * 2] - mn);
                float p1 = exp2f(s[nt][hf * 2 + 1] - mn);
                s[nt][hf * 2] = p0;
                s[nt][hf * 2 + 1] = p1;
                rs += p0 + p1;
            }
            rs += __shfl_xor_sync(0xffffffffu, rs, 1);
            rs += __shfl_xor_sync(0xffffffffu, rs, 2);
            l_[hf] = l_[hf] * corr + rs;
#pragma unroll
            for (int nt = 0; nt < 8; nt++) {
                o_[nt][hf * 2] *= corr;
                o_[nt][hf * 2 + 1] *= corr;
            }
        }

        // ---- O += P V (P from registers; V g2-pair + term-major)
#pragma unroll
        for (int ks = 0; ks < 4; ks++) {
            uint32_t pa_h[4], pa_l[4];
            pa_h[0] = pack_split(s[2 * ks][0], s[2 * ks][1], pa_l[0]);
            pa_h[1] = pack_split(s[2 * ks][2], s[2 * ks][3], pa_l[1]);
            pa_h[2] = pack_split(s[2 * ks + 1][0], s[2 * ks + 1][1], pa_l[2]);
            pa_h[3] = pack_split(s[2 * ks + 1][2], s[2 * ks + 1][3], pa_l[3]);
            const int k0 = ks * 16;
#pragma unroll
            for (int g2p = 0; g2p < 2; g2p++) {
                uint32_t vh[2][4], vl[2][4];
#pragma unroll
                for (int j = 0; j < 2; j++) {
                    uint32_t offV = 2u * (uint32_t)((k0 + vRowOff) * FST +
                                                    (g2p * 2 + j) * 16 + vColOff);
                    ldsm_x4_t(vh[j][0], vh[j][1], vh[j][2], vh[j][3], kvB + 2u * KV_VH + offV);
                    ldsm_x4_t(vl[j][0], vl[j][1], vl[j][2], vl[j][3], kvB + 2u * KV_VL + offV);
                }
#pragma unroll
                for (int term = 0; term < 3; term++)
#pragma unroll
                    for (int j = 0; j < 2; j++)
#pragma unroll
                        for (int half = 0; half < 2; half++) {
                            const int nt = (g2p * 2 + j) * 2 + half, p = half * 2;
                            if (term == 0)
                                mma_bf16(o_[nt], pa_h, vh[j][p], vh[j][p + 1]);
                            else if (term == 1)
                                mma_bf16(o_[nt], pa_h, vl[j][p], vl[j][p + 1]);
                            else
                                mma_bf16(o_[nt], pa_l, vh[j][p], vh[j][p + 1]);
                        }
            }
        }

        if (kt < 15) CP_WAIT0();
        __syncthreads();
    }

    // ---- normalize + store O as bf16 hi/lo (same split the GEMM would do)
    const float inv0 = 1.0f / l_[0];
    const float inv1 = 1.0f / l_[1];
    const int row = q0 + w * 16 + (l >> 2);
#pragma unroll
    for (int nt = 0; nt < 8; nt++) {
        int col = h * DHEAD + nt * 8 + 2 * (l & 3);
        long i0 = ((long)b * SEQ + row) * EMB + col;
        long i1 = ((long)b * SEQ + row + 8) * EMB + col;
        __nv_bfloat162 lo0, lo1;
        __nv_bfloat162 hi0 = split_hi(o_[nt][0] * inv0, o_[nt][1] * inv0, lo0);
        __nv_bfloat162 hi1 = split_hi(o_[nt][2] * inv1, o_[nt][3] * inv1, lo1);
        *(__nv_bfloat162*)(g_o_hi + i0) = hi0;
        *(__nv_bfloat162*)(g_o_lo + i0) = lo0;
        *(__nv_bfloat162*)(g_o_hi + i1) = hi1;
        *(__nv_bfloat162*)(g_o_lo + i1) = lo1;
    }
}

// ---------------- launch ---------------------------------------------------
extern "C" void kernel_launch(void* const* d_in, const int* in_sizes, int n_in,
                              void* d_out, int out_size) {
    const float* z    = (const float*)d_in[0];
    const float* Uqkv = (const float*)d_in[1];
    const float* Umsa = (const float*)d_in[2];
    float* out        = (float*)d_out;

    cudaFuncSetAttribute(flash_kernel, cudaFuncAttributeMaxDynamicSharedMemorySize, FLASH_SMEM);
    cudaFuncSetAttribute(hmma_gemm_kernel<QKVN, 1>,
                         cudaFuncAttributeMaxDynamicSharedMemorySize, GEMM_SMEM);
    cudaFuncSetAttribute(hmma_gemm_kernel<EMB, 2>,
                         cudaFuncAttributeMaxDynamicSharedMemorySize, GEMM_SMEM);

    pack_z_kernel<<<(NTOK * EMB / 2 + 255) / 256, 256>>>(z);
    pack_qkv_kernel<<<(QKVN * EMB + 255) / 256, 256>>>(Uqkv);
    pack_msa_kernel<<<(EMB * EMB + 255) / 256, 256>>>(Umsa);

    hmma_gemm_kernel<QKVN, 1><<<dim3(QKVN / 128, NTOK / 128), 256, GEMM_SMEM>>>(nullptr);

    flash_kernel<<<dim3(SEQ / 128, BATCH, NUM_HEAD), 256, FLASH_SMEM>>>();

    hmma_gemm_kernel<EMB, 2><<<dim3(EMB / 128, NTOK / 128), 256, GEMM_SMEM>>>(out);
}

// round 17
// speedup vs baseline: 1.1397x; 1.1120x over previous
#include <cuda_runtime.h>
#include <cuda_fp16.h>
#include <cstdint>

#define NUM_HEAD 12
#define BATCH    16
#define SEQ      1024
#define DHEAD    64
#define EMB      768
#define QKVN     2304   // 3 * 12 * 64
#define NTOK     (BATCH * SEQ)

// ======================= scratch (device globals) ==========================
__device__ __half g_q_hi[NUM_HEAD * BATCH * SEQ * DHEAD];  // [h][b][n][d]
__device__ __half g_q_lo[NUM_HEAD * BATCH * SEQ * DHEAD];
__device__ __half g_k_hi[NUM_HEAD * BATCH * SEQ * DHEAD];
__device__ __half g_k_lo[NUM_HEAD * BATCH * SEQ * DHEAD];
__device__ __half g_v_hi[NUM_HEAD * BATCH * SEQ * DHEAD];
__device__ __half g_v_lo[NUM_HEAD * BATCH * SEQ * DHEAD];
__device__ float  g_o[NTOK * EMB];                         // attn out f32 [tok][h*d]
__device__ __half g_Wq_hi[QKVN * EMB];                     // QKV weights T [c][e]
__device__ __half g_Wq_lo[QKVN * EMB];
__device__ __half g_Wm_hi[EMB * EMB];                      // Umsa T [n][e]
__device__ __half g_Wm_lo[EMB * EMB];

// ======================= split helpers (fp16) ==============================
__device__ __forceinline__ __half2 split_hi(float a, float b, __half2& lo) {
    __half ha = __float2half_rn(a);
    __half hb = __float2half_rn(b);
    lo = __halves2half2(__float2half_rn(a - __half2float(ha)),
                        __float2half_rn(b - __half2float(hb)));
    return __halves2half2(ha, hb);
}
__device__ __forceinline__ uint32_t pack_h2(float a, float b) {
    __half2 h = __halves2half2(__float2half_rn(a), __float2half_rn(b));
    return *(uint32_t*)&h;
}

// ---------------- fused weight packing: f32 -> transposed fp16 hi/lo -------
__global__ void pack_w_kernel(const float* __restrict__ Uqkv,
                              const float* __restrict__ Umsa) {
    int idx = blockIdx.x * blockDim.x + threadIdx.x;
    if (idx < QKVN * EMB) {
        int c = idx / EMB, e = idx - c * EMB;
        int h = c / 192, rem = c - h * 192;
        int r = rem >> 6, d = rem & 63;
        float v = Uqkv[((h * 3 + r) * EMB + e) * DHEAD + d];
        __half hi = __float2half_rn(v);
        g_Wq_hi[idx] = hi;
        g_Wq_lo[idx] = __float2half_rn(v - __half2float(hi));
    } else if (idx < QKVN * EMB + EMB * EMB) {
        int j = idx - QKVN * EMB;
        int n = j / EMB, e = j - n * EMB;
        float v = Umsa[e * EMB + n];
        __half hi = __float2half_rn(v);
        g_Wm_hi[j] = hi;
        g_Wm_lo[j] = __float2half_rn(v - __half2float(hi));
    }
}

// ======================= warp-MMA / async helpers ==========================
__device__ __forceinline__ void ldsm_x4(uint32_t& r0, uint32_t& r1, uint32_t& r2, uint32_t& r3,
                                        uint32_t addr) {
    asm volatile("ldmatrix.sync.aligned.m8n8.x4.shared.b16 {%0,%1,%2,%3}, [%4];"
                 : "=r"(r0), "=r"(r1), "=r"(r2), "=r"(r3)
                 : "r"(addr));
}
__device__ __forceinline__ void ldsm_x4_t(uint32_t& r0, uint32_t& r1, uint32_t& r2, uint32_t& r3,
                                          uint32_t addr) {
    asm volatile("ldmatrix.sync.aligned.m8n8.x4.trans.shared.b16 {%0,%1,%2,%3}, [%4];"
                 : "=r"(r0), "=r"(r1), "=r"(r2), "=r"(r3)
                 : "r"(addr));
}
__device__ __forceinline__ void mma_f16(float* c, const uint32_t* a, uint32_t b0, uint32_t b1) {
    asm volatile(
        "mma.sync.aligned.m16n8k16.row.col.f32.f16.f16.f32 "
        "{%0,%1,%2,%3}, {%4,%5,%6,%7}, {%8,%9}, {%0,%1,%2,%3};"
        : "+f"(c[0]), "+f"(c[1]), "+f"(c[2]), "+f"(c[3])
        : "r"(a[0]), "r"(a[1]), "r"(a[2]), "r"(a[3]), "r"(b0), "r"(b1));
}
__device__ __forceinline__ void cp_async16(uint32_t smem_addr, const void* gptr) {
    asm volatile("cp.async.cg.shared.global [%0], [%1], 16;" :: "r"(smem_addr), "l"(gptr));
}
#define CP_COMMIT() asm volatile("cp.async.commit_group;" ::: "memory")
#define CP_WAIT0()  asm volatile("cp.async.wait_group 0;" ::: "memory")

// ===== split-fp16 HMMA GEMM: C = A * B^T, 128x128 tile =====================
// A f32 (split in-loop); B pre-split fp16 hi/lo via cp.async. 3-term split.
#define AST   40
#define G_AH  0
#define G_AL  (128 * AST)
#define G_BH  (2 * 128 * AST)
#define G_BL  (3 * 128 * AST)
#define G_BUF (4 * 128 * AST)          // 20480 elems per buffer
#define GEMM_SMEM (2 * G_BUF * 2)      // 81920 bytes

template <int NC, int MODE>
__global__ void __launch_bounds__(256, 2) hmma_gemm_kernel(const float* __restrict__ Ap,
                                                           float* __restrict__ Cp) {
    extern __shared__ __half gsm[];
    const int t = threadIdx.x, w = t >> 5, l = t & 31;
    const int n0 = blockIdx.x * 128, m0 = blockIdx.y * 128;
    const int wm = w >> 1, wn = w & 1;

    const float* A = (MODE == 2) ? (const float*)g_o : Ap;
    const __half* Bhg = (MODE == 1) ? (const __half*)g_Wq_hi : (const __half*)g_Wm_hi;
    const __half* Blg = (MODE == 1) ? (const __half*)g_Wq_lo : (const __half*)g_Wm_lo;

    float acc[2][8][4];
#pragma unroll
    for (int mt = 0; mt < 2; mt++)
#pragma unroll
        for (int nt = 0; nt < 8; nt++)
#pragma unroll
            for (int r = 0; r < 4; r++) acc[mt][nt][r] = 0.0f;

    const uint32_t smB = (uint32_t)__cvta_generic_to_shared(gsm);

    const int aRow = wm * 32 + (l & 15);            // + mt*16
    const int aCol = (l >> 4) << 3;
    const int bRowOff = (l & 7) + ((l >> 4) << 3);  // + wn*64 + g2*16
    const int bCol = ((l >> 3) & 1) << 3;

    const int arow = t >> 3, ac4 = (t & 7) << 2;    // A: 32 rows/pass, 4 iters
    const int brow = t >> 2, bc8 = (t & 3) << 3;    // B: 64 rows/pass, 2 iters

    float4 aP[4];

    auto ldgA = [&](int kc) {
#pragma unroll
        for (int i = 0; i < 4; i++)
            aP[i] = *(const float4*)(A + (long)(m0 + arow + i * 32) * 768 + kc + ac4);
    };
    auto cpB = [&](int kc, uint32_t bufEl) {
#pragma unroll
        for (int i = 0; i < 2; i++) {
            int row = brow + i * 64;
            uint32_t off = 2u * (uint32_t)(row * AST + bc8);
            cp_async16(smB + 2u * (bufEl + G_BH) + off, Bhg + (long)(n0 + row) * 768 + kc + bc8);
            cp_async16(smB + 2u * (bufEl + G_BL) + off, Blg + (long)(n0 + row) * 768 + kc + bc8);
        }
    };
    auto stsA = [&](uint32_t bufEl) {
#pragma unroll
        for (int i = 0; i < 4; i++) {
            __half2 l01, l23;
            __half2 h01 = split_hi(aP[i].x, aP[i].y, l01);
            __half2 h23 = split_hi(aP[i].z, aP[i].w, l23);
            int off = (arow + i * 32) * AST + ac4;
            *(uint2*)&gsm[bufEl + G_AH + off] = make_uint2(*(uint32_t*)&h01, *(uint32_t*)&h23);
            *(uint2*)&gsm[bufEl + G_AL + off] = make_uint2(*(uint32_t*)&l01, *(uint32_t*)&l23);
        }
    };

    ldgA(0);
    cpB(0, 0);
    CP_COMMIT();
    stsA(0);
    CP_WAIT0();
    __syncthreads();

    for (int c = 0; c < 24; c++) {
        const uint32_t cur = (uint32_t)(c & 1) * G_BUF;
        const uint32_t nxt = (uint32_t)((c + 1) & 1) * G_BUF;
        if (c < 23) {
            ldgA((c + 1) * 32);
            cpB((c + 1) * 32, nxt);
            CP_COMMIT();
        }

        const uint32_t aHB = smB + 2u * (cur + G_AH), aLB = smB + 2u * (cur + G_AL);
        const uint32_t bHB = smB + 2u * (cur + G_BH), bLB = smB + 2u * (cur + G_BL);
#pragma unroll
        for (int ks = 0; ks < 2; ks++) {
            const int k0 = ks * 16;
            uint32_t ah[2][4], al[2][4];
#pragma unroll
            for (int mt = 0; mt < 2; mt++) {
                uint32_t off = 2u * (uint32_t)((aRow + mt * 16) * AST + k0 + aCol);
                ldsm_x4(ah[mt][0], ah[mt][1], ah[mt][2], ah[mt][3], aHB + off);
                ldsm_x4(al[mt][0], al[mt][1], al[mt][2], al[mt][3], aLB + off);
            }
#pragma unroll
            for (int g2 = 0; g2 < 4; g2++) {
                uint32_t bh[4], bl[4];
                uint32_t off =
                    2u * (uint32_t)((wn * 64 + g2 * 16 + bRowOff) * AST + k0 + bCol);
                ldsm_x4(bh[0], bh[1], bh[2], bh[3], bHB + off);
                ldsm_x4(bl[0], bl[1], bl[2], bl[3], bLB + off);
#pragma unroll
                for (int half = 0; half < 2; half++) {
                    const int nt = g2 * 2 + half, p = half * 2;
#pragma unroll
                    for (int mt = 0; mt < 2; mt++) {
                        mma_f16(acc[mt][nt], ah[mt], bh[p], bh[p + 1]);
                        mma_f16(acc[mt][nt], ah[mt], bl[p], bl[p + 1]);
                        mma_f16(acc[mt][nt], al[mt], bh[p], bh[p + 1]);
                    }
                }
            }
        }

        if (c < 23) {
            stsA(nxt);
            CP_WAIT0();
        }
        __syncthreads();
    }

    // ---- epilogue
    const int rBase = m0 + wm * 32 + (l >> 2);
    const int cBase = wn * 64 + 2 * (l & 3);
    if (MODE == 2) {
#pragma unroll
        for (int mt = 0; mt < 2; mt++)
#pragma unroll
            for (int nt = 0; nt < 8; nt++) {
                int rA = rBase + mt * 16;
                int c = n0 + cBase + nt * 8;
                *(float2*)(Cp + (long)rA * NC + c) = make_float2(acc[mt][nt][0], acc[mt][nt][1]);
                *(float2*)(Cp + (long)(rA + 8) * NC + c) =
                    make_float2(acc[mt][nt][2], acc[mt][nt][3]);
            }
    } else {
        // QKV epilogue: q/k/v in natural [h][b][n][d] fp16 hi/lo
        const int g = (n0 + wn * 64) >> 6;  // h*3 + r
        const int h = g / 3, r = g - h * 3;
        __half* dh = (r == 0 ? g_q_hi : (r == 1 ? g_k_hi : g_v_hi));
        __half* dl = (r == 0 ? g_q_lo : (r == 1 ? g_k_lo : g_v_lo));
#pragma unroll
        for (int mt = 0; mt < 2; mt++) {
            int m = rBase + mt * 16;
            int b = m >> 10, tok = m & 1023;
            int hb = h * BATCH + b;
#pragma unroll
            for (int nt = 0; nt < 8; nt++) {
                int d = 2 * (l & 3) + nt * 8;
                long i0 = ((long)hb * SEQ + tok) * DHEAD + d;
                __half2 lo01, lo23;
                __half2 hi01 = split_hi(acc[mt][nt][0], acc[mt][nt][1], lo01);
                __half2 hi23 = split_hi(acc[mt][nt][2], acc[mt][nt][3], lo23);
                *(__half2*)(dh + i0) = hi01;
                *(__half2*)(dl + i0) = lo01;
                *(__half2*)(dh + i0 + 8 * DHEAD) = hi23;
                *(__half2*)(dl + i0 + 8 * DHEAD) = lo23;
            }
        }
    }
}

// ========= flash attention: fp16 split; QK 3-term, PV 2-term ===============
#define FST 72
#define FQ_H 0
#define FQ_L (128 * FST)
#define FKV0 (2 * 128 * FST)
#define KV_KL (64 * FST)
#define KV_VH (2 * 64 * FST)
#define KV_VL (3 * 64 * FST)
#define KV_BUF (4 * 64 * FST)
#define FLASH_SMEM ((2 * 128 * FST + 2 * KV_BUF) * 2)   // 110592 bytes

__global__ void __launch_bounds__(256, 2) flash_kernel() {
    extern __shared__ __half sm[];
    const int t = threadIdx.x, w = t >> 5, l = t & 31;
    const int h = blockIdx.z, b = blockIdx.y, q0 = blockIdx.x * 128;
    const int hb = h * BATCH + b;
    const float SC = 0.125f * 1.4426950408889634f;

    const __half* Qh = g_q_hi + ((long)hb * SEQ + q0) * DHEAD;
    const __half* Ql = g_q_lo + ((long)hb * SEQ + q0) * DHEAD;
    const __half* Kh = g_k_hi + (long)hb * SEQ * DHEAD;
    const __half* Kl = g_k_lo + (long)hb * SEQ * DHEAD;
    const __half* Vh = g_v_hi + (long)hb * SEQ * DHEAD;
    const __half* Vl = g_v_lo + (long)hb * SEQ * DHEAD;

    const uint32_t smB = (uint32_t)__cvta_generic_to_shared(sm);
    const int lrow = t >> 3, lc8 = (t & 7) << 3;

    auto cpKV = [&](int kb, uint32_t bufEl) {
#pragma unroll
        for (int i = 0; i < 2; i++) {
            int row = lrow + i * 32;
            uint32_t off = 2u * (uint32_t)(row * FST + lc8);
            cp_async16(smB + 2u * bufEl + off, Kh + (long)(kb + row) * DHEAD + lc8);
            cp_async16(smB + 2u * (bufEl + KV_KL) + off, Kl + (long)(kb + row) * DHEAD + lc8);
            cp_async16(smB + 2u * (bufEl + KV_VH) + off, Vh + (long)(kb + row) * DHEAD + lc8);
            cp_async16(smB + 2u * (bufEl + KV_VL) + off, Vl + (long)(kb + row) * DHEAD + lc8);
        }
    };

    cpKV(0, FKV0);
    CP_COMMIT();
#pragma unroll
    for (int i = 0; i < 4; i++) {
        int idx = t + i * 256;
        int row = idx >> 3, c8 = (idx & 7) << 3;
        *(uint4*)&sm[FQ_H + row * FST + c8] = *(const uint4*)(Qh + (long)row * DHEAD + c8);
        *(uint4*)&sm[FQ_L + row * FST + c8] = *(const uint4*)(Ql + (long)row * DHEAD + c8);
    }
    CP_WAIT0();
    __syncthreads();

    float m_[2], l_[2], o_[8][4];
    m_[0] = m_[1] = -1e30f;
    l_[0] = l_[1] = 0.0f;
#pragma unroll
    for (int nt = 0; nt < 8; nt++)
#pragma unroll
        for (int r = 0; r < 4; r++) o_[nt][r] = 0.0f;

    const int aRowOff = w * 16 + (l & 15);
    const int aColOff = (l >> 4) << 3;
    const int bRowOff = (l & 7) + ((l >> 4) << 3);        // K (non-trans B)
    const int bColOff = ((l >> 3) & 1) << 3;
    const int vRowOff = (l & 7) + (((l >> 3) & 1) << 3);  // V (trans B): row = key
    const int vColOff = (l >> 4) << 3;                    //              col = dv

    for (int kt = 0; kt < 16; kt++) {
        const uint32_t cur = FKV0 + (uint32_t)(kt & 1) * KV_BUF;
        if (kt < 15) {
            cpKV((kt + 1) * 64, FKV0 + (uint32_t)((kt + 1) & 1) * KV_BUF);
            CP_COMMIT();
        }
        const uint32_t kvB = smB + 2u * cur;

        // ---- S = Q K^T, 3-term split
        float s[8][4];
#pragma unroll
        for (int nt = 0; nt < 8; nt++)
#pragma unroll
            for (int r = 0; r < 4; r++) s[nt][r] = 0.0f;
#pragma unroll
        for (int ks = 0; ks < 4; ks++) {
            const int k0 = ks * 16;
            uint32_t qh[4], ql[4];
            uint32_t offA = 2u * (uint32_t)(aRowOff * FST + k0 + aColOff);
            ldsm_x4(qh[0], qh[1], qh[2], qh[3], smB + (FQ_H * 2) + offA);
            ldsm_x4(ql[0], ql[1], ql[2], ql[3], smB + (FQ_L * 2) + offA);
#pragma unroll
            for (int g2 = 0; g2 < 4; g2++) {
                uint32_t kh[4], kl[4];
                uint32_t offB = 2u * (uint32_t)((bRowOff + g2 * 16) * FST + k0 + bColOff);
                ldsm_x4(kh[0], kh[1], kh[2], kh[3], kvB + offB);
                ldsm_x4(kl[0], kl[1], kl[2], kl[3], kvB + 2u * KV_KL + offB);
#pragma unroll
                for (int half = 0; half < 2; half++) {
                    const int nt = g2 * 2 + half, p = half * 2;
                    mma_f16(s[nt], qh, kh[p], kh[p + 1]);
                    mma_f16(s[nt], qh, kl[p], kl[p + 1]);
                    mma_f16(s[nt], ql, kh[p], kh[p + 1]);
                }
            }
        }

        // ---- scale + online softmax (warp-local rows)
#pragma unroll
        for (int nt = 0; nt < 8; nt++)
#pragma unroll
            for (int r = 0; r < 4; r++) s[nt][r] *= SC;

#pragma unroll
        for (int hf = 0; hf < 2; hf++) {
            float mx = -1e30f;
#pragma unroll
            for (int nt = 0; nt < 8; nt++)
                mx = fmaxf(mx, fmaxf(s[nt][hf * 2], s[nt][hf * 2 + 1]));
            mx = fmaxf(mx, __shfl_xor_sync(0xffffffffu, mx, 1));
            mx = fmaxf(mx, __shfl_xor_sync(0xffffffffu, mx, 2));
            float mn = fmaxf(m_[hf], mx);
            float corr = exp2f(m_[hf] - mn);
            m_[hf] = mn;
            float rs = 0.0f;
#pragma unroll
            for (int nt = 0; nt < 8; nt++) {
                float p0 = exp2f(s[nt][hf * 2] - mn);
                float p1 = exp2f(s[nt][hf * 2 + 1] - mn);
                s[nt][hf * 2] = p0;
                s[nt][hf * 2 + 1] = p1;
                rs += p0 + p1;
            }
            rs += __shfl_xor_sync(0xffffffffu, rs, 1);
            rs += __shfl_xor_sync(0xffffffffu, rs, 2);
            l_[hf] = l_[hf] * corr + rs;
#pragma unroll
            for (int nt = 0; nt < 8; nt++) {
                o_[nt][hf * 2] *= corr;
                o_[nt][hf * 2 + 1] *= corr;
            }
        }

        // ---- O += P V, 2-term: Ph*(Vh + Vl); Pl*V dropped (~2^-12 rel)
#pragma unroll
        for (int ks = 0; ks < 4; ks++) {
            uint32_t pa[4];
            pa[0] = pack_h2(s[2 * ks][0], s[2 * ks][1]);
            pa[1] = pack_h2(s[2 * ks][2], s[2 * ks][3]);
            pa[2] = pack_h2(s[2 * ks + 1][0], s[2 * ks + 1][1]);
            pa[3] = pack_h2(s[2 * ks + 1][2], s[2 * ks + 1][3]);
            const int k0 = ks * 16;
#pragma unroll
            for (int g2 = 0; g2 < 4; g2++) {
                uint32_t vh[4], vl[4];
                uint32_t offV =
                    2u * (uint32_t)((k0 + vRowOff) * FST + g2 * 16 + vColOff);
                ldsm_x4_t(vh[0], vh[1], vh[2], vh[3], kvB + 2u * KV_VH + offV);
                ldsm_x4_t(vl[0], vl[1], vl[2], vl[3], kvB + 2u * KV_VL + offV);
#pragma unroll
                for (int half = 0; half < 2; half++) {
                    const int nt = g2 * 2 + half, p = half * 2;
                    mma_f16(o_[nt], pa, vh[p], vh[p + 1]);
                    mma_f16(o_[nt], pa, vl[p], vl[p + 1]);
                }
            }
        }

        if (kt < 15) CP_WAIT0();
        __syncthreads();
    }

    // ---- normalize + store O f32 to g_o [b][n][h*64 + d]
    const float inv0 = 1.0f / l_[0];
    const float inv1 = 1.0f / l_[1];
    const int row = q0 + w * 16 + (l >> 2);
#pragma unroll
    for (int nt = 0; nt < 8; nt++) {
        int col = h * DHEAD + nt * 8 + 2 * (l & 3);
        *(float2*)(g_o + ((long)b * SEQ + row) * EMB + col) =
            make_float2(o_[nt][0] * inv0, o_[nt][1] * inv0);
        *(float2*)(g_o + ((long)b * SEQ + row + 8) * EMB + col) =
            make_float2(o_[nt][2] * inv1, o_[nt][3] * inv1);
    }
}

// ---------------- launch ---------------------------------------------------
extern "C" void kernel_launch(void* const* d_in, const int* in_sizes, int n_in,
                              void* d_out, int out_size) {
    const float* z    = (const float*)d_in[0];
    const float* Uqkv = (const float*)d_in[1];
    const float* Umsa = (const float*)d_in[2];
    float* out        = (float*)d_out;

    cudaFuncSetAttribute(flash_kernel, cudaFuncAttributeMaxDynamicSharedMemorySize, FLASH_SMEM);
    cudaFuncSetAttribute(hmma_gemm_kernel<QKVN, 1>,
                         cudaFuncAttributeMaxDynamicSharedMemorySize, GEMM_SMEM);
    cudaFuncSetAttribute(hmma_gemm_kernel<EMB, 2>,
                         cudaFuncAttributeMaxDynamicSharedMemorySize, GEMM_SMEM);

    const int packN = QKVN * EMB + EMB * EMB;
    pack_w_kernel<<<(packN + 255) / 256, 256>>>(Uqkv, Umsa);

    hmma_gemm_kernel<QKVN, 1><<<dim3(QKVN / 128, NTOK / 128), 256, GEMM_SMEM>>>(z, nullptr);

    flash_kernel<<<dim3(SEQ / 128, BATCH, NUM_HEAD), 256, FLASH_SMEM>>>();

    hmma_gemm_kernel<EMB, 2><<<dim3(EMB / 128, NTOK / 128), 256, GEMM_SMEM>>>(nullptr, out);
}